// round 1
// baseline (speedup 1.0000x reference)
#include <cuda_runtime.h>
#include <cuda_bf16.h>
#include <math.h>

// Problem constants
#define BB 2
#define SS 2048
#define FF_IN 64
#define EE 512
#define HH 8
#define DH 64
#define LL 4
#define FFN 2048
#define MM (BB * SS)          // 4096 tokens
#define ATTN_SCALE 0.044194173824159216f   // 1/sqrt(512)

// ---------------------------------------------------------------------------
// Scratch (device globals; allocation-free per harness rules)
// ---------------------------------------------------------------------------
__device__ float g_X[MM * EE];
__device__ float g_Q[MM * EE];
__device__ float g_K[MM * EE];
__device__ float g_V[MM * EE];
__device__ float g_ATT[MM * EE];
__device__ float g_P[MM * EE];
__device__ float g_H1[MM * FFN];

// ---------------------------------------------------------------------------
// Embedding: X[m, :] = seq[m, :] @ W_emb + b_emb + pos_emb[s, :]
// grid = MM blocks, 128 threads (each thread: 4 contiguous output cols)
// ---------------------------------------------------------------------------
__global__ __launch_bounds__(128) void embed_kernel(
    const float* __restrict__ seq, const float* __restrict__ W,
    const float* __restrict__ bias, const float* __restrict__ pos,
    float* __restrict__ X)
{
    int m = blockIdx.x;
    int s = m & (SS - 1);
    int tid = threadIdx.x;
    __shared__ float srow[FF_IN];
    if (tid < FF_IN) srow[tid] = seq[(size_t)m * FF_IN + tid];
    __syncthreads();
    int n = tid * 4;
    float4 acc = *(const float4*)(bias + n);
    float4 pv  = *(const float4*)(pos + (size_t)s * EE + n);
    acc.x += pv.x; acc.y += pv.y; acc.z += pv.z; acc.w += pv.w;
    #pragma unroll 8
    for (int f = 0; f < FF_IN; f++) {
        float sv = srow[f];
        float4 w = *(const float4*)(W + (size_t)f * EE + n);
        acc.x += sv * w.x; acc.y += sv * w.y; acc.z += sv * w.z; acc.w += sv * w.w;
    }
    *(float4*)(X + (size_t)m * EE + n) = acc;
}

// ---------------------------------------------------------------------------
// SGEMM: C[M,N] = A[M,K] @ B[K,N] + bias[N]  (optional ReLU)
// BM=128, BN=64, BK=16; 256 threads; 8x4 micro-tile per thread.
// M, N, K all divisible by tile dims for this problem (no guards).
// ---------------------------------------------------------------------------
template <bool RELU>
__global__ __launch_bounds__(256) void sgemm_kernel(
    const float* __restrict__ A, const float* __restrict__ B,
    const float* __restrict__ bias, float* __restrict__ C,
    int N, int K)
{
    __shared__ float As[16][128];
    __shared__ float Bs[16][64];

    const int tid  = threadIdx.x;
    const int cRow = blockIdx.y * 128;
    const int cCol = blockIdx.x * 64;
    const int tr   = tid >> 4;        // 0..15 -> 8 rows each
    const int tc   = tid & 15;        // 0..15 -> 4 cols each
    const int aRow = tid >> 1;        // 0..127
    const int aCol = (tid & 1) * 8;   // 0 or 8
    const int bRow = tid >> 4;        // 0..15
    const int bCol = (tid & 15) * 4;  // 0..60

    float acc[8][4];
    #pragma unroll
    for (int i = 0; i < 8; i++)
        #pragma unroll
        for (int j = 0; j < 4; j++) acc[i][j] = 0.f;

    const float* Ap = A + (size_t)cRow * K;
    const float* Bp = B + cCol;

    for (int k0 = 0; k0 < K; k0 += 16) {
        float4 a0 = *(const float4*)(Ap + (size_t)aRow * K + k0 + aCol);
        float4 a1 = *(const float4*)(Ap + (size_t)aRow * K + k0 + aCol + 4);
        As[aCol + 0][aRow] = a0.x; As[aCol + 1][aRow] = a0.y;
        As[aCol + 2][aRow] = a0.z; As[aCol + 3][aRow] = a0.w;
        As[aCol + 4][aRow] = a1.x; As[aCol + 5][aRow] = a1.y;
        As[aCol + 6][aRow] = a1.z; As[aCol + 7][aRow] = a1.w;
        float4 bv = *(const float4*)(Bp + (size_t)(k0 + bRow) * N + bCol);
        *(float4*)&Bs[bRow][bCol] = bv;
        __syncthreads();

        #pragma unroll
        for (int k = 0; k < 16; k++) {
            float ar[8], br[4];
            *(float4*)&ar[0] = *(const float4*)&As[k][tr * 8];
            *(float4*)&ar[4] = *(const float4*)&As[k][tr * 8 + 4];
            *(float4*)&br[0] = *(const float4*)&Bs[k][tc * 4];
            #pragma unroll
            for (int i = 0; i < 8; i++)
                #pragma unroll
                for (int j = 0; j < 4; j++)
                    acc[i][j] += ar[i] * br[j];
        }
        __syncthreads();
    }

    float4 bb = *(const float4*)(bias + cCol + tc * 4);
    #pragma unroll
    for (int i = 0; i < 8; i++) {
        float4 r;
        r.x = acc[i][0] + bb.x;
        r.y = acc[i][1] + bb.y;
        r.z = acc[i][2] + bb.z;
        r.w = acc[i][3] + bb.w;
        if (RELU) {
            r.x = fmaxf(r.x, 0.f); r.y = fmaxf(r.y, 0.f);
            r.z = fmaxf(r.z, 0.f); r.w = fmaxf(r.w, 0.f);
        }
        *(float4*)(C + (size_t)(cRow + tr * 8 + i) * N + cCol + tc * 4) = r;
    }
}

// ---------------------------------------------------------------------------
// Flash attention. One CTA: 64 query rows x one (batch, head). Loops over
// 64-key tiles with online softmax. K tile buffer is reused to hold P.
// Dynamic smem: Qs[64][64] (swizzled), KP[64][64] (swizzled), Vs[64][68], Ms[64].
// grid = (S/64, B*H), 256 threads (16x16).
// ---------------------------------------------------------------------------
#define ATTN_SMEM ((64 * 64 + 64 * 64 + 64 * 68) * 4 + 64 * 4)

__global__ __launch_bounds__(256) void attn_kernel(
    const float* __restrict__ Qg, const float* __restrict__ Kg,
    const float* __restrict__ Vg, const int* __restrict__ mask,
    float* __restrict__ Og)
{
    extern __shared__ float smem[];
    float* Qs = smem;                 // 64*64, xor-swizzled
    float* KP = smem + 4096;          // 64*64, xor-swizzled (K, then P)
    float* Vs = smem + 8192;          // 64*68 padded
    int*   Ms = (int*)(smem + 12544); // 64

    const int tid = threadIdx.x;
    const int ty  = tid >> 4;   // 0..15
    const int tx  = tid & 15;   // 0..15
    const int ty4 = ty * 4;
    const int tx4 = tx * 4;
    const int sQ  = ty & 7;     // swizzle key for rows ty4..ty4+3
    const int sK  = tx & 7;     // swizzle key for rows tx4..tx4+3

    const int bh = blockIdx.y;
    const int b  = bh >> 3;
    const int h  = bh & 7;
    const int qrow0 = blockIdx.x * 64;

    // cooperative load mapping: each thread 1 row (lr), 4 float4 groups
    const int lr  = tid >> 2;          // 0..63
    const int lcg = (tid & 3) * 4;     // base float4-group
    const int swl = (lr >> 2) & 7;

    // Load Q (scaled) into swizzled Qs
    {
        const float* qp = Qg + (size_t)(b * SS + qrow0 + lr) * EE + h * DH;
        #pragma unroll
        for (int u = 0; u < 4; u++) {
            int d4 = lcg + u;
            float4 v = *(const float4*)(qp + d4 * 4);
            v.x *= ATTN_SCALE; v.y *= ATTN_SCALE; v.z *= ATTN_SCALE; v.w *= ATTN_SCALE;
            *(float4*)&Qs[lr * 64 + ((d4 ^ swl) << 2)] = v;
        }
    }

    float m_i[4], l_i[4], o[4][4];
    #pragma unroll
    for (int i = 0; i < 4; i++) {
        m_i[i] = -INFINITY; l_i[i] = 0.f;
        #pragma unroll
        for (int j = 0; j < 4; j++) o[i][j] = 0.f;
    }

    for (int kt = 0; kt < SS / 64; kt++) {
        __syncthreads();   // prev-iter P@V reads done (and Q visible on iter 0)
        {
            const float* kp = Kg + (size_t)(b * SS + kt * 64 + lr) * EE + h * DH;
            const float* vp = Vg + (size_t)(b * SS + kt * 64 + lr) * EE + h * DH;
            #pragma unroll
            for (int u = 0; u < 4; u++) {
                int d4 = lcg + u;
                float4 kv = *(const float4*)(kp + d4 * 4);
                *(float4*)&KP[lr * 64 + ((d4 ^ swl) << 2)] = kv;
                float4 vv = *(const float4*)(vp + d4 * 4);
                *(float4*)&Vs[lr * 68 + d4 * 4] = vv;
            }
            if (tid < 64) Ms[tid] = mask[b * SS + kt * 64 + tid];
        }
        __syncthreads();

        // S tile = Qs @ KP^T  (each thread 4x4)
        float s[4][4];
        #pragma unroll
        for (int i = 0; i < 4; i++)
            #pragma unroll
            for (int j = 0; j < 4; j++) s[i][j] = 0.f;

        #pragma unroll 4
        for (int d4 = 0; d4 < 16; d4++) {
            float4 qv[4], kv[4];
            #pragma unroll
            for (int i = 0; i < 4; i++)
                qv[i] = *(const float4*)&Qs[(ty4 + i) * 64 + ((d4 ^ sQ) << 2)];
            #pragma unroll
            for (int j = 0; j < 4; j++)
                kv[j] = *(const float4*)&KP[(tx4 + j) * 64 + ((d4 ^ sK) << 2)];
            #pragma unroll
            for (int i = 0; i < 4; i++)
                #pragma unroll
                for (int j = 0; j < 4; j++)
                    s[i][j] += qv[i].x * kv[j].x + qv[i].y * kv[j].y +
                               qv[i].z * kv[j].z + qv[i].w * kv[j].w;
        }

        // mask (all-ones in this dataset, honored anyway)
        #pragma unroll
        for (int j = 0; j < 4; j++) {
            if (Ms[tx4 + j] == 0) {
                #pragma unroll
                for (int i = 0; i < 4; i++) s[i][j] = -1e20f;
            }
        }

        // online softmax update (row stats reduced over the 16-lane tx group)
        #pragma unroll
        for (int i = 0; i < 4; i++) {
            float mx = fmaxf(fmaxf(s[i][0], s[i][1]), fmaxf(s[i][2], s[i][3]));
            #pragma unroll
            for (int off = 8; off; off >>= 1)
                mx = fmaxf(mx, __shfl_xor_sync(0xffffffffu, mx, off));
            float mnew = fmaxf(m_i[i], mx);
            float corr = __expf(m_i[i] - mnew);
            float rs = 0.f;
            #pragma unroll
            for (int j = 0; j < 4; j++) {
                float p = __expf(s[i][j] - mnew);
                s[i][j] = p;
                rs += p;
            }
            #pragma unroll
            for (int off = 8; off; off >>= 1)
                rs += __shfl_xor_sync(0xffffffffu, rs, off);
            l_i[i] = l_i[i] * corr + rs;
            m_i[i] = mnew;
            #pragma unroll
            for (int j = 0; j < 4; j++) o[i][j] *= corr;
        }

        __syncthreads();   // everyone finished reading K tile

        // store P into KP (same swizzle: d4 ^ (row>>2 & 7); here row>>2 == ty)
        #pragma unroll
        for (int i = 0; i < 4; i++) {
            float4 pv = make_float4(s[i][0], s[i][1], s[i][2], s[i][3]);
            *(float4*)&KP[(ty4 + i) * 64 + ((tx ^ sQ) << 2)] = pv;
        }
        __syncthreads();

        // O += P @ V
        #pragma unroll 2
        for (int k4 = 0; k4 < 16; k4++) {
            float4 pr[4], vv[4];
            #pragma unroll
            for (int i = 0; i < 4; i++)
                pr[i] = *(const float4*)&KP[(ty4 + i) * 64 + ((k4 ^ sQ) << 2)];
            #pragma unroll
            for (int jj = 0; jj < 4; jj++)
                vv[jj] = *(const float4*)&Vs[(k4 * 4 + jj) * 68 + tx4];
            #pragma unroll
            for (int i = 0; i < 4; i++) {
                o[i][0] += pr[i].x * vv[0].x + pr[i].y * vv[1].x + pr[i].z * vv[2].x + pr[i].w * vv[3].x;
                o[i][1] += pr[i].x * vv[0].y + pr[i].y * vv[1].y + pr[i].z * vv[2].y + pr[i].w * vv[3].y;
                o[i][2] += pr[i].x * vv[0].z + pr[i].y * vv[1].z + pr[i].z * vv[2].z + pr[i].w * vv[3].z;
                o[i][3] += pr[i].x * vv[0].w + pr[i].y * vv[1].w + pr[i].z * vv[2].w + pr[i].w * vv[3].w;
            }
        }
    }

    // finalize and write out
    #pragma unroll
    for (int i = 0; i < 4; i++) {
        float inv = 1.f / l_i[i];
        float4 r = make_float4(o[i][0] * inv, o[i][1] * inv, o[i][2] * inv, o[i][3] * inv);
        *(float4*)(Og + (size_t)(b * SS + qrow0 + ty4 + i) * EE + h * DH + tx4) = r;
    }
}

// ---------------------------------------------------------------------------
// Fused residual + LayerNorm: out[m,:] = LN(a[m,:] + br[m,:]) * g + be
// grid = MM blocks, 128 threads.
// ---------------------------------------------------------------------------
__global__ __launch_bounds__(128) void ln_kernel(
    const float* __restrict__ a, const float* __restrict__ br,
    const float* __restrict__ g, const float* __restrict__ be,
    float* __restrict__ out)
{
    int m = blockIdx.x;
    int tid = threadIdx.x;
    size_t base = (size_t)m * EE + tid * 4;
    float4 va = *(const float4*)(a + base);
    float4 vb = *(const float4*)(br + base);
    float x0 = va.x + vb.x, x1 = va.y + vb.y, x2 = va.z + vb.z, x3 = va.w + vb.w;
    float s  = x0 + x1 + x2 + x3;
    float ss = x0 * x0 + x1 * x1 + x2 * x2 + x3 * x3;
    #pragma unroll
    for (int off = 16; off; off >>= 1) {
        s  += __shfl_xor_sync(0xffffffffu, s, off);
        ss += __shfl_xor_sync(0xffffffffu, ss, off);
    }
    __shared__ float red[8];
    int w = tid >> 5, ln = tid & 31;
    if (ln == 0) { red[w] = s; red[4 + w] = ss; }
    __syncthreads();
    s  = red[0] + red[1] + red[2] + red[3];
    ss = red[4] + red[5] + red[6] + red[7];
    float mean = s * (1.f / EE);
    float var  = ss * (1.f / EE) - mean * mean;
    float r = rsqrtf(var + 1e-5f);
    float4 gg = *(const float4*)(g + tid * 4);
    float4 bb = *(const float4*)(be + tid * 4);
    float4 o;
    o.x = (x0 - mean) * r * gg.x + bb.x;
    o.y = (x1 - mean) * r * gg.y + bb.y;
    o.z = (x2 - mean) * r * gg.z + bb.z;
    o.w = (x3 - mean) * r * gg.w + bb.w;
    *(float4*)(out + base) = o;
}

// ---------------------------------------------------------------------------
// Launch
// ---------------------------------------------------------------------------
extern "C" void kernel_launch(void* const* d_in, const int* in_sizes, int n_in,
                              void* d_out, int out_size)
{
    const float* seq   = (const float*)d_in[0];
    const int*   mask  = (const int*)  d_in[1];
    const float* W_emb = (const float*)d_in[2];
    const float* b_emb = (const float*)d_in[3];
    const float* pos   = (const float*)d_in[4];
    const float* Wq    = (const float*)d_in[5];
    const float* bq    = (const float*)d_in[6];
    const float* Wk    = (const float*)d_in[7];
    const float* bk    = (const float*)d_in[8];
    const float* Wv    = (const float*)d_in[9];
    const float* bv    = (const float*)d_in[10];
    const float* Wo    = (const float*)d_in[11];
    const float* bo    = (const float*)d_in[12];
    const float* ln1g  = (const float*)d_in[13];
    const float* ln1b  = (const float*)d_in[14];
    const float* ln2g  = (const float*)d_in[15];
    const float* ln2b  = (const float*)d_in[16];
    const float* W1    = (const float*)d_in[17];
    const float* b1    = (const float*)d_in[18];
    const float* W2    = (const float*)d_in[19];
    const float* b2    = (const float*)d_in[20];
    float* out = (float*)d_out;

    float *X, *Q, *K, *V, *ATT, *P, *H1;
    cudaGetSymbolAddress((void**)&X,   g_X);
    cudaGetSymbolAddress((void**)&Q,   g_Q);
    cudaGetSymbolAddress((void**)&K,   g_K);
    cudaGetSymbolAddress((void**)&V,   g_V);
    cudaGetSymbolAddress((void**)&ATT, g_ATT);
    cudaGetSymbolAddress((void**)&P,   g_P);
    cudaGetSymbolAddress((void**)&H1,  g_H1);

    cudaFuncSetAttribute(attn_kernel, cudaFuncAttributeMaxDynamicSharedMemorySize,
                         ATTN_SMEM);

    embed_kernel<<<MM, 128>>>(seq, W_emb, b_emb, pos, X);

    dim3 gemmE(EE / 64, MM / 128);     // N=512
    dim3 gemmF(FFN / 64, MM / 128);    // N=2048
    dim3 attnG(SS / 64, BB * HH);

    for (int l = 0; l < LL; l++) {
        size_t oW  = (size_t)l * EE * EE;
        size_t oB  = (size_t)l * EE;
        size_t oW1 = (size_t)l * EE * FFN;
        size_t oB1 = (size_t)l * FFN;
        size_t oW2 = (size_t)l * FFN * EE;

        sgemm_kernel<false><<<gemmE, 256>>>(X, Wq + oW, bq + oB, Q, EE, EE);
        sgemm_kernel<false><<<gemmE, 256>>>(X, Wk + oW, bk + oB, K, EE, EE);
        sgemm_kernel<false><<<gemmE, 256>>>(X, Wv + oW, bv + oB, V, EE, EE);

        attn_kernel<<<attnG, 256, ATTN_SMEM>>>(Q, K, V, mask, ATT);

        sgemm_kernel<false><<<gemmE, 256>>>(ATT, Wo + oW, bo + oB, P, EE, EE);
        ln_kernel<<<MM, 128>>>(X, P, ln1g + oB, ln1b + oB, X);

        sgemm_kernel<true ><<<gemmF, 256>>>(X, W1 + oW1, b1 + oB1, H1, FFN, EE);
        sgemm_kernel<false><<<gemmE, 256>>>(H1, W2 + oW2, b2 + oB, P, EE, FFN);

        float* dst = (l == LL - 1) ? out : X;
        ln_kernel<<<MM, 128>>>(X, P, ln2g + oB, ln2b + oB, dst);
    }
}